// round 1
// baseline (speedup 1.0000x reference)
#include <cuda_runtime.h>

#define NNODES 50000
#define NEDGES 800000
#define TOTEDGES (NEDGES + NNODES)

// ---------------- scratch (no allocations allowed) ----------------
__device__ float g_h[NNODES * 128];     // GEMM output (pre-aggregation features)
__device__ float g_bufA[NNODES * 128];  // layer activations ping
__device__ float g_bufB[NNODES * 128];  // layer activations pong
__device__ float g_es[NNODES * 4];      // per-node per-head src attention logits
__device__ float g_ed[NNODES * 4];      // per-node per-head dst attention logits
__device__ float g_stats[256];          // BN sum / sumsq
__device__ int   g_deg[NNODES];
__device__ int   g_rowptr[NNODES + 1];
__device__ int   g_cursor[NNODES];
__device__ int   g_csr[TOTEDGES];       // source node id per (dst-sorted) edge

// ---------------- CSR build ----------------
__global__ void deg_init_kernel(int* deg) {
    int i = blockIdx.x * blockDim.x + threadIdx.x;
    if (i < NNODES) deg[i] = 1;  // self loop
}

__global__ void count_kernel(const int* __restrict__ dst, int* __restrict__ deg) {
    int i = blockIdx.x * blockDim.x + threadIdx.x;
    if (i < NEDGES) atomicAdd(&deg[dst[i]], 1);
}

__global__ void scan_kernel(const int* __restrict__ deg, int* __restrict__ rowptr,
                            int* __restrict__ cursor) {
    __shared__ int part[1024];
    const int CH = (NNODES + 1023) / 1024;
    int t = threadIdx.x;
    int base = t * CH;
    int s = 0;
    for (int i = 0; i < CH; i++) {
        int idx = base + i;
        if (idx < NNODES) s += deg[idx];
    }
    part[t] = s;
    __syncthreads();
    for (int off = 1; off < 1024; off <<= 1) {
        int v = (t >= off) ? part[t - off] : 0;
        __syncthreads();
        part[t] += v;
        __syncthreads();
    }
    int run = (t == 0) ? 0 : part[t - 1];
    for (int i = 0; i < CH; i++) {
        int idx = base + i;
        if (idx < NNODES) {
            rowptr[idx] = run;
            cursor[idx] = run;
            run += deg[idx];
        }
    }
    if (t == 1023) rowptr[NNODES] = part[1023];
}

__global__ void scatter_self_kernel(int* __restrict__ cursor, int* __restrict__ csr) {
    int i = blockIdx.x * blockDim.x + threadIdx.x;
    if (i < NNODES) {
        int pos = atomicAdd(&cursor[i], 1);
        csr[pos] = i;
    }
}

__global__ void scatter_edges_kernel(const int* __restrict__ src, const int* __restrict__ dst,
                                     int* __restrict__ cursor, int* __restrict__ csr) {
    int i = blockIdx.x * blockDim.x + threadIdx.x;
    if (i < NEDGES) {
        int d = dst[i];
        int pos = atomicAdd(&cursor[d], 1);
        csr[pos] = src[i];
    }
}

// ---------------- SGEMM: C[M,N] = A[M,K] @ B[K,N], row-major ----------------
template <int BM, int BN, int BK, int TM, int TN>
__global__ void gemm_kernel(const float* __restrict__ A, const float* __restrict__ B,
                            float* __restrict__ C, int M, int K, int N) {
    constexpr int TX = BN / TN;
    constexpr int TY = BM / TM;
    constexpr int NT = TX * TY;
    __shared__ float As[BM][BK + 1];
    __shared__ float Bs[BK][BN + 1];
    const int tx = threadIdx.x, ty = threadIdx.y;
    const int t = ty * TX + tx;
    const int rowBase = blockIdx.x * BM;
    float acc[TM][TN];
#pragma unroll
    for (int i = 0; i < TM; i++)
#pragma unroll
        for (int j = 0; j < TN; j++) acc[i][j] = 0.f;

    for (int k0 = 0; k0 < K; k0 += BK) {
        for (int i = t; i < BM * BK; i += NT) {
            int m = i / BK, kk = i % BK;
            int r = rowBase + m;
            As[m][kk] = (r < M) ? A[r * K + k0 + kk] : 0.f;
        }
        for (int i = t; i < BK * BN; i += NT) {
            int kk = i / BN, c = i % BN;
            Bs[kk][c] = B[(k0 + kk) * N + c];
        }
        __syncthreads();
#pragma unroll
        for (int kk = 0; kk < BK; kk++) {
            float a[TM], b[TN];
#pragma unroll
            for (int i = 0; i < TM; i++) a[i] = As[ty + TY * i][kk];
#pragma unroll
            for (int j = 0; j < TN; j++) b[j] = Bs[kk][tx + TX * j];
#pragma unroll
            for (int i = 0; i < TM; i++)
#pragma unroll
                for (int j = 0; j < TN; j++) acc[i][j] += a[i] * b[j];
        }
        __syncthreads();
    }
#pragma unroll
    for (int i = 0; i < TM; i++) {
        int r = rowBase + ty + TY * i;
        if (r < M) {
#pragma unroll
            for (int j = 0; j < TN; j++) C[r * N + tx + TX * j] = acc[i][j];
        }
    }
}

// ---------------- attention logits: es/ed[n,h] = <h[n,h,:], a[h,:]> ----------------
template <int H, int D>
__global__ void attn_kernel(const float* __restrict__ h, const float* __restrict__ asrc,
                            const float* __restrict__ adst, float* __restrict__ es,
                            float* __restrict__ ed, int n) {
    int idx = blockIdx.x * blockDim.x + threadIdx.x;
    if (idx >= n * H) return;
    int node = idx / H, hh = idx % H;
    const float4* hp = reinterpret_cast<const float4*>(h + (size_t)node * H * D + hh * D);
    const float4* ap = reinterpret_cast<const float4*>(asrc + hh * D);
    const float4* bp = reinterpret_cast<const float4*>(adst + hh * D);
    float s = 0.f, dv = 0.f;
#pragma unroll
    for (int i = 0; i < D / 4; i++) {
        float4 v = hp[i], a = ap[i], b = bp[i];
        s += v.x * a.x + v.y * a.y + v.z * a.z + v.w * a.w;
        dv += v.x * b.x + v.y * b.y + v.z * b.z + v.w * b.w;
    }
    es[idx] = s;
    ed[idx] = dv;
}

// ---------------- aggregation (one CTA per destination node) ----------------
__device__ __forceinline__ float lrelu(float a) { return a > 0.f ? a : 0.2f * a; }

template <int H>
__device__ __forceinline__ void load_esv(const float* __restrict__ es, int s, float* v) {
    if constexpr (H == 4) {
        float4 t = *reinterpret_cast<const float4*>(es + s * 4);
        v[0] = t.x; v[1] = t.y; v[2] = t.z; v[3] = t.w;
    } else {
        v[0] = es[s];
    }
}

template <int H, int D, bool RELU>
__global__ void agg_kernel(const float* __restrict__ hbuf, const float* __restrict__ es,
                           const float* __restrict__ ed, const int* __restrict__ rowptr,
                           const int* __restrict__ csr, const float* __restrict__ bias,
                           float* __restrict__ out) {
    constexpr int C = H * D;
    const int node = blockIdx.x;
    const int tid = threadIdx.x;
    const int start = rowptr[node];
    const int deg = rowptr[node + 1] - start;

    __shared__ float s_ed[H];
    __shared__ float s_mx[H];
    __shared__ float s_inv[H];
    __shared__ float s_all[H * C];
    __shared__ float s_w[C * H];
    __shared__ int s_src[C];

    if (tid < H) s_ed[tid] = ed[node * H + tid];
    __syncthreads();
    float edv[H];
#pragma unroll
    for (int hh = 0; hh < H; hh++) edv[hh] = s_ed[hh];

    // pass 1: segment max per head
    float mx[H];
#pragma unroll
    for (int hh = 0; hh < H; hh++) mx[hh] = -1e30f;
    for (int e = tid; e < deg; e += C) {
        int s = csr[start + e];
        float ev[H];
        load_esv<H>(es, s, ev);
#pragma unroll
        for (int hh = 0; hh < H; hh++) mx[hh] = fmaxf(mx[hh], lrelu(ev[hh] + edv[hh]));
    }
#pragma unroll
    for (int hh = 0; hh < H; hh++) s_all[hh * C + tid] = mx[hh];
    __syncthreads();
    if (tid < H) {
        float m = -1e30f;
        for (int j = 0; j < C; j++) m = fmaxf(m, s_all[tid * C + j]);
        s_mx[tid] = m;
    }
    __syncthreads();
#pragma unroll
    for (int hh = 0; hh < H; hh++) mx[hh] = s_mx[hh];

    // pass 2: softmax denominator
    float sm[H];
#pragma unroll
    for (int hh = 0; hh < H; hh++) sm[hh] = 0.f;
    for (int e = tid; e < deg; e += C) {
        int s = csr[start + e];
        float ev[H];
        load_esv<H>(es, s, ev);
#pragma unroll
        for (int hh = 0; hh < H; hh++) sm[hh] += __expf(lrelu(ev[hh] + edv[hh]) - mx[hh]);
    }
#pragma unroll
    for (int hh = 0; hh < H; hh++) s_all[hh * C + tid] = sm[hh];
    __syncthreads();
    if (tid < H) {
        float tsum = 0.f;
        for (int j = 0; j < C; j++) tsum += s_all[tid * C + j];
        s_inv[tid] = 1.f / tsum;
    }
    __syncthreads();
    float inv[H];
#pragma unroll
    for (int hh = 0; hh < H; hh++) inv[hh] = s_inv[hh];

    // pass 3: weighted gather (chunked)
    float acc = 0.f;
    const int head = tid / D;
    for (int base = 0; base < deg; base += C) {
        int cn = min(C, deg - base);
        __syncthreads();
        if (tid < cn) {
            int s = csr[start + base + tid];
            s_src[tid] = s;
            float ev[H];
            load_esv<H>(es, s, ev);
#pragma unroll
            for (int hh = 0; hh < H; hh++)
                s_w[tid * H + hh] = __expf(lrelu(ev[hh] + edv[hh]) - mx[hh]) * inv[hh];
        }
        __syncthreads();
#pragma unroll 4
        for (int j = 0; j < cn; j++) {
            acc += s_w[j * H + head] * hbuf[(size_t)s_src[j] * C + tid];
        }
    }
    float r = acc + bias[tid];
    if (RELU) r = fmaxf(r, 0.f);
    out[(size_t)node * C + tid] = r;
}

// ---------------- batchnorm ----------------
__global__ void zero_stats_kernel(float* stats) {
    stats[threadIdx.x] = 0.f;
}

__global__ void bn_stats_kernel(const float* __restrict__ x, float* __restrict__ stats, int C) {
    __shared__ float shs[512], shq[512];
    int c = threadIdx.x, ry = threadIdx.y;
    int R = blockDim.y;
    int r0 = blockIdx.x * 256;
    int rend = min(r0 + 256, NNODES);
    float s = 0.f, q = 0.f;
    for (int r = r0 + ry; r < rend; r += R) {
        float v = x[(size_t)r * C + c];
        s += v;
        q += v * v;
    }
    int t = ry * C + c;
    shs[t] = s;
    shq[t] = q;
    __syncthreads();
    if (ry == 0) {
        for (int k = 1; k < R; k++) {
            s += shs[k * C + c];
            q += shq[k * C + c];
        }
        atomicAdd(&stats[c], s);
        atomicAdd(&stats[C + c], q);
    }
}

__global__ void bn_apply_kernel(float* __restrict__ x, const float* __restrict__ stats,
                                const float* __restrict__ g, const float* __restrict__ be,
                                int C, int relu) {
    const float invn = 1.f / (float)NNODES;
    int total = NNODES * C;
    for (int idx = blockIdx.x * blockDim.x + threadIdx.x; idx < total;
         idx += gridDim.x * blockDim.x) {
        int c = idx % C;
        float mean = stats[c] * invn;
        float var = stats[C + c] * invn - mean * mean;
        float sc = g[c] * rsqrtf(var + 1e-5f);
        float v = (x[idx] - mean) * sc + be[c];
        if (relu) v = fmaxf(v, 0.f);
        x[idx] = v;
    }
}

// ---------------- host launch ----------------
extern "C" void kernel_launch(void* const* d_in, const int* in_sizes, int n_in,
                              void* d_out, int out_size) {
    const float* x   = (const float*)d_in[0];
    const int*   ei  = (const int*)d_in[1];
    const float* W1  = (const float*)d_in[2];
    const float* as1 = (const float*)d_in[3];
    const float* ad1 = (const float*)d_in[4];
    const float* b1  = (const float*)d_in[5];
    const float* g1  = (const float*)d_in[6];
    const float* be1 = (const float*)d_in[7];
    const float* W2  = (const float*)d_in[8];
    const float* as2 = (const float*)d_in[9];
    const float* ad2 = (const float*)d_in[10];
    const float* b2  = (const float*)d_in[11];
    const float* g2  = (const float*)d_in[12];
    const float* be2 = (const float*)d_in[13];
    const float* W3  = (const float*)d_in[14];
    const float* as3 = (const float*)d_in[15];
    const float* ad3 = (const float*)d_in[16];
    const float* b3  = (const float*)d_in[17];
    const float* W4  = (const float*)d_in[18];
    const float* as4 = (const float*)d_in[19];
    const float* ad4 = (const float*)d_in[20];
    const float* b4  = (const float*)d_in[21];
    const float* g4  = (const float*)d_in[22];
    const float* be4 = (const float*)d_in[23];
    const float* W5  = (const float*)d_in[24];
    const float* as5 = (const float*)d_in[25];
    const float* ad5 = (const float*)d_in[26];
    const float* b5  = (const float*)d_in[27];
    float* out = (float*)d_out;

    float *h, *bufA, *bufB, *es, *ed, *stats;
    int *deg, *rowptr, *cursor, *csr;
    cudaGetSymbolAddress((void**)&h, g_h);
    cudaGetSymbolAddress((void**)&bufA, g_bufA);
    cudaGetSymbolAddress((void**)&bufB, g_bufB);
    cudaGetSymbolAddress((void**)&es, g_es);
    cudaGetSymbolAddress((void**)&ed, g_ed);
    cudaGetSymbolAddress((void**)&stats, g_stats);
    cudaGetSymbolAddress((void**)&deg, g_deg);
    cudaGetSymbolAddress((void**)&rowptr, g_rowptr);
    cudaGetSymbolAddress((void**)&cursor, g_cursor);
    cudaGetSymbolAddress((void**)&csr, g_csr);

    const int* e_src = ei;
    const int* e_dst = ei + NEDGES;

    // ---- build dst-CSR (shared across all 5 layers) ----
    deg_init_kernel<<<(NNODES + 255) / 256, 256>>>(deg);
    count_kernel<<<(NEDGES + 255) / 256, 256>>>(e_dst, deg);
    scan_kernel<<<1, 1024>>>(deg, rowptr, cursor);
    scatter_self_kernel<<<(NNODES + 255) / 256, 256>>>(cursor, csr);
    scatter_edges_kernel<<<(NEDGES + 255) / 256, 256>>>(e_src, e_dst, cursor, csr);

    const int MBLK = (NNODES + 127) / 128;
    dim3 gblk(16, 16);

    // ---- layer 1: GAT(128 -> 4x32), relu, bn ----
    gemm_kernel<128, 128, 32, 8, 8><<<MBLK, gblk>>>(x, W1, h, NNODES, 128, 128);
    attn_kernel<4, 32><<<(NNODES * 4 + 255) / 256, 256>>>(h, as1, ad1, es, ed, NNODES);
    agg_kernel<4, 32, true><<<NNODES, 128>>>(h, es, ed, rowptr, csr, b1, bufA);
    zero_stats_kernel<<<1, 256>>>(stats);
    bn_stats_kernel<<<(NNODES + 255) / 256, dim3(128, 4)>>>(bufA, stats, 128);
    bn_apply_kernel<<<512, 256>>>(bufA, stats, g1, be1, 128, 0);

    // ---- layer 2: GAT(128 -> 4x32), relu, bn ----
    gemm_kernel<128, 128, 32, 8, 8><<<MBLK, gblk>>>(bufA, W2, h, NNODES, 128, 128);
    attn_kernel<4, 32><<<(NNODES * 4 + 255) / 256, 256>>>(h, as2, ad2, es, ed, NNODES);
    agg_kernel<4, 32, true><<<NNODES, 128>>>(h, es, ed, rowptr, csr, b2, bufB);
    zero_stats_kernel<<<1, 256>>>(stats);
    bn_stats_kernel<<<(NNODES + 255) / 256, dim3(128, 4)>>>(bufB, stats, 128);
    bn_apply_kernel<<<512, 256>>>(bufB, stats, g2, be2, 128, 0);

    // ---- layer 3: GAT(128 -> 32), relu ----
    gemm_kernel<128, 32, 32, 8, 2><<<MBLK, gblk>>>(bufB, W3, h, NNODES, 128, 32);
    attn_kernel<1, 32><<<(NNODES + 255) / 256, 256>>>(h, as3, ad3, es, ed, NNODES);
    agg_kernel<1, 32, true><<<NNODES, 32>>>(h, es, ed, rowptr, csr, b3, bufA);

    // ---- layer 4: GAT(32 -> 32), relu, bn, relu ----
    gemm_kernel<128, 32, 32, 8, 2><<<MBLK, gblk>>>(bufA, W4, h, NNODES, 32, 32);
    attn_kernel<1, 32><<<(NNODES + 255) / 256, 256>>>(h, as4, ad4, es, ed, NNODES);
    agg_kernel<1, 32, true><<<NNODES, 32>>>(h, es, ed, rowptr, csr, b4, bufB);
    zero_stats_kernel<<<1, 256>>>(stats);
    bn_stats_kernel<<<(NNODES + 255) / 256, dim3(32, 16)>>>(bufB, stats, 32);
    bn_apply_kernel<<<512, 256>>>(bufB, stats, g4, be4, 32, 1);

    // ---- layer 5: GAT(32 -> 128), no relu, output ----
    gemm_kernel<128, 128, 32, 8, 8><<<MBLK, gblk>>>(bufB, W5, h, NNODES, 32, 128);
    attn_kernel<1, 128><<<(NNODES + 255) / 256, 256>>>(h, as5, ad5, es, ed, NNODES);
    agg_kernel<1, 128, false><<<NNODES, 128>>>(h, es, ed, rowptr, csr, b5, out);
}

// round 2
// speedup vs baseline: 1.3564x; 1.3564x over previous
#include <cuda_runtime.h>

#define NNODES 50000
#define NEDGES 800000
#define TOTEDGES (NEDGES + NNODES)

// ---------------- scratch (no allocations allowed) ----------------
__device__ float g_h[NNODES * 128];     // GEMM output (pre-aggregation features)
__device__ float g_bufA[NNODES * 128];  // layer activations ping
__device__ float g_bufB[NNODES * 128];  // layer activations pong
__device__ float g_es[NNODES * 4];      // per-node per-head src attention logits
__device__ float g_ed[NNODES * 4];      // per-node per-head dst attention logits
__device__ float g_stats[256];          // BN sum / sumsq
__device__ int   g_deg[NNODES];
__device__ int   g_rowptr[NNODES + 1];
__device__ int   g_cursor[NNODES];
__device__ int   g_csr[TOTEDGES];       // source node id per (dst-sorted) edge

// ---------------- CSR build ----------------
__global__ void deg_init_kernel(int* deg) {
    int i = blockIdx.x * blockDim.x + threadIdx.x;
    if (i < NNODES) deg[i] = 1;  // self loop
}

__global__ void count_kernel(const int* __restrict__ dst, int* __restrict__ deg) {
    int i = blockIdx.x * blockDim.x + threadIdx.x;
    if (i < NEDGES) atomicAdd(&deg[dst[i]], 1);
}

__global__ void scan_kernel(const int* __restrict__ deg, int* __restrict__ rowptr,
                            int* __restrict__ cursor) {
    __shared__ int part[1024];
    const int CH = (NNODES + 1023) / 1024;
    int t = threadIdx.x;
    int base = t * CH;
    int s = 0;
    for (int i = 0; i < CH; i++) {
        int idx = base + i;
        if (idx < NNODES) s += deg[idx];
    }
    part[t] = s;
    __syncthreads();
    for (int off = 1; off < 1024; off <<= 1) {
        int v = (t >= off) ? part[t - off] : 0;
        __syncthreads();
        part[t] += v;
        __syncthreads();
    }
    int run = (t == 0) ? 0 : part[t - 1];
    for (int i = 0; i < CH; i++) {
        int idx = base + i;
        if (idx < NNODES) {
            rowptr[idx] = run;
            cursor[idx] = run;
            run += deg[idx];
        }
    }
    if (t == 1023) rowptr[NNODES] = part[1023];
}

__global__ void scatter_self_kernel(int* __restrict__ cursor, int* __restrict__ csr) {
    int i = blockIdx.x * blockDim.x + threadIdx.x;
    if (i < NNODES) {
        int pos = atomicAdd(&cursor[i], 1);
        csr[pos] = i;
    }
}

__global__ void scatter_edges_kernel(const int* __restrict__ src, const int* __restrict__ dst,
                                     int* __restrict__ cursor, int* __restrict__ csr) {
    int i = blockIdx.x * blockDim.x + threadIdx.x;
    if (i < NEDGES) {
        int d = dst[i];
        int pos = atomicAdd(&cursor[d], 1);
        csr[pos] = src[i];
    }
}

// ---------------- SGEMM: C = A @ B, row-major, optional fused BN-affine on A ----------------
// AFFINE: A' = A*sc + sh where sc = g*rsqrt(var+eps), sh = be - mean*sc (per column of A)
// INRELU: A' = max(A', 0)  (for layer5 which consumes relu(bn(r)))
template <int BM, int BN, int BK, int TM, int TN, bool AFFINE, bool INRELU>
__global__ void gemm_kernel(const float* __restrict__ A, const float* __restrict__ B,
                            float* __restrict__ C, int M, int K, int N,
                            const float* __restrict__ stats, const float* __restrict__ g,
                            const float* __restrict__ be) {
    constexpr int TX = BN / TN;
    constexpr int TY = BM / TM;
    constexpr int NT = TX * TY;
    __shared__ float As[BM][BK + 1];
    __shared__ float Bs[BK * BN];
    __shared__ float s_sc[128];
    __shared__ float s_sh[128];

    const int tx = threadIdx.x, ty = threadIdx.y;
    const int t = ty * TX + tx;
    const int rowBase = blockIdx.x * BM;

    if (AFFINE) {
        const float invn = 1.f / (float)NNODES;
        for (int c = t; c < K; c += NT) {
            float mean = stats[c] * invn;
            float var = stats[K + c] * invn - mean * mean;
            float scv = g[c] * rsqrtf(var + 1e-5f);
            s_sc[c] = scv;
            s_sh[c] = be[c] - mean * scv;
        }
        __syncthreads();
    }

    float acc[TM][TN];
#pragma unroll
    for (int i = 0; i < TM; i++)
#pragma unroll
        for (int j = 0; j < TN; j++) acc[i][j] = 0.f;

    for (int k0 = 0; k0 < K; k0 += BK) {
        // A tile: BM x BK, float4 loads
        for (int i = t * 4; i < BM * BK; i += NT * 4) {
            int m = i / BK, kk = i % BK;
            int r = rowBase + m;
            float4 v = make_float4(0.f, 0.f, 0.f, 0.f);
            if (r < M) v = *reinterpret_cast<const float4*>(A + (size_t)r * K + k0 + kk);
            if (AFFINE) {
                int c = k0 + kk;
                v.x = v.x * s_sc[c] + s_sh[c];
                v.y = v.y * s_sc[c + 1] + s_sh[c + 1];
                v.z = v.z * s_sc[c + 2] + s_sh[c + 2];
                v.w = v.w * s_sc[c + 3] + s_sh[c + 3];
                if (INRELU) {
                    v.x = fmaxf(v.x, 0.f); v.y = fmaxf(v.y, 0.f);
                    v.z = fmaxf(v.z, 0.f); v.w = fmaxf(v.w, 0.f);
                }
            }
            As[m][kk] = v.x; As[m][kk + 1] = v.y; As[m][kk + 2] = v.z; As[m][kk + 3] = v.w;
        }
        // B tile: BK x BN, float4 loads (BN == N)
        for (int i = t * 4; i < BK * BN; i += NT * 4) {
            int kk = i / BN, c = i % BN;
            *reinterpret_cast<float4*>(&Bs[kk * BN + c]) =
                *reinterpret_cast<const float4*>(B + (size_t)(k0 + kk) * N + c);
        }
        __syncthreads();
#pragma unroll
        for (int kk = 0; kk < BK; kk++) {
            float a[TM], b[TN];
#pragma unroll
            for (int i = 0; i < TM; i++) a[i] = As[ty + TY * i][kk];
#pragma unroll
            for (int j = 0; j < TN; j++) b[j] = Bs[kk * BN + tx + TX * j];
#pragma unroll
            for (int i = 0; i < TM; i++)
#pragma unroll
                for (int j = 0; j < TN; j++) acc[i][j] += a[i] * b[j];
        }
        __syncthreads();
    }
#pragma unroll
    for (int i = 0; i < TM; i++) {
        int r = rowBase + ty + TY * i;
        if (r < M) {
#pragma unroll
            for (int j = 0; j < TN; j++) C[(size_t)r * N + tx + TX * j] = acc[i][j];
        }
    }
}

// ---------------- attention logits (+ fused stats zeroing) ----------------
template <int H, int D>
__global__ void attn_kernel(const float* __restrict__ h, const float* __restrict__ asrc,
                            const float* __restrict__ adst, float* __restrict__ es,
                            float* __restrict__ ed, int n, float* __restrict__ stats, int zn) {
    int idx = blockIdx.x * blockDim.x + threadIdx.x;
    if (idx < zn) stats[idx] = 0.f;
    if (idx >= n * H) return;
    int node = idx / H, hh = idx % H;
    const float4* hp = reinterpret_cast<const float4*>(h + (size_t)node * H * D + hh * D);
    const float4* ap = reinterpret_cast<const float4*>(asrc + hh * D);
    const float4* bp = reinterpret_cast<const float4*>(adst + hh * D);
    float s = 0.f, dv = 0.f;
#pragma unroll
    for (int i = 0; i < D / 4; i++) {
        float4 v = hp[i], a = ap[i], b = bp[i];
        s += v.x * a.x + v.y * a.y + v.z * a.z + v.w * a.w;
        dv += v.x * b.x + v.y * b.y + v.z * b.z + v.w * b.w;
    }
    es[idx] = s;
    ed[idx] = dv;
}

// ---------------- aggregation ----------------
__device__ __forceinline__ float lrelu(float a) { return a > 0.f ? a : 0.2f * a; }
__device__ __forceinline__ float ew(float z) { return __expf(fminf(z, 70.f)); }

template <int H>
__device__ __forceinline__ void load_esv(const float* __restrict__ es, int s, float* v) {
    if constexpr (H == 4) {
        float4 t = *reinterpret_cast<const float4*>(es + s * 4);
        v[0] = t.x; v[1] = t.y; v[2] = t.z; v[3] = t.w;
    } else {
        v[0] = es[s];
    }
}

// block-per-node variant for C = H*D = 128
template <int H, int D, bool RELU>
__global__ void agg_kernel(const float* __restrict__ hbuf, const float* __restrict__ es,
                           const float* __restrict__ ed, const int* __restrict__ rowptr,
                           const int* __restrict__ csr, const float* __restrict__ bias,
                           float* __restrict__ out) {
    constexpr int C = H * D;
    constexpr int NW = C / 32;
    const int node = blockIdx.x;
    const int tid = threadIdx.x;
    const int lane = tid & 31;
    const int wrp = tid >> 5;
    const int start = rowptr[node];
    const int deg = rowptr[node + 1] - start;

    __shared__ float s_ed[H];
    __shared__ float s_inv[H];
    __shared__ float s_red[NW * H];
    __shared__ float s_w[C * H];
    __shared__ int s_src[C];

    if (tid < H) s_ed[tid] = ed[node * H + tid];
    __syncthreads();
    float edv[H];
#pragma unroll
    for (int hh = 0; hh < H; hh++) edv[hh] = s_ed[hh];

    // pass A: softmax denominator (no max pass; logits are O(1)); stage chunk-0 weights
    float sm[H];
#pragma unroll
    for (int hh = 0; hh < H; hh++) sm[hh] = 0.f;
    for (int e = tid; e < deg; e += C) {
        int s = csr[start + e];
        float evv[H], w[H];
        load_esv<H>(es, s, evv);
#pragma unroll
        for (int hh = 0; hh < H; hh++) w[hh] = ew(lrelu(evv[hh] + edv[hh]));
        if (e < C) {
            s_src[e] = s;
#pragma unroll
            for (int hh = 0; hh < H; hh++) s_w[e * H + hh] = w[hh];
        }
#pragma unroll
        for (int hh = 0; hh < H; hh++) sm[hh] += w[hh];
    }
#pragma unroll
    for (int hh = 0; hh < H; hh++) {
#pragma unroll
        for (int off = 16; off; off >>= 1) sm[hh] += __shfl_xor_sync(0xffffffffu, sm[hh], off);
    }
    if (lane == 0) {
#pragma unroll
        for (int hh = 0; hh < H; hh++) s_red[wrp * H + hh] = sm[hh];
    }
    __syncthreads();
    if (tid < H) {
        float tsum = 0.f;
#pragma unroll
        for (int w2 = 0; w2 < NW; w2++) tsum += s_red[w2 * H + tid];
        s_inv[tid] = 1.f / tsum;
    }
    __syncthreads();

    const int head = tid / D;
    const float inv = s_inv[head];

    // pass B: weighted gather (chunk 0 uses staged weights; tail chunks are rare)
    float acc = 0.f;
    int cn0 = min(deg, C);
#pragma unroll 4
    for (int j = 0; j < cn0; j++) {
        acc += s_w[j * H + head] * hbuf[(size_t)s_src[j] * C + tid];
    }
    for (int base = C; base < deg; base += C) {
        int cn = min(C, deg - base);
        __syncthreads();
        if (tid < cn) {
            int s = csr[start + base + tid];
            s_src[tid] = s;
            float evv[H];
            load_esv<H>(es, s, evv);
#pragma unroll
            for (int hh = 0; hh < H; hh++) s_w[tid * H + hh] = ew(lrelu(evv[hh] + edv[hh]));
        }
        __syncthreads();
#pragma unroll 4
        for (int j = 0; j < cn; j++) {
            acc += s_w[j * H + head] * hbuf[(size_t)s_src[j] * C + tid];
        }
    }
    float r = acc * inv + bias[tid];
    if (RELU) r = fmaxf(r, 0.f);
    out[(size_t)node * C + tid] = r;
}

// warp-per-node variant for C = 32 (H=1, D=32); NPB nodes per block
template <int NPB, bool RELU>
__global__ void agg_warp_kernel(const float* __restrict__ hbuf, const float* __restrict__ es,
                                const float* __restrict__ ed, const int* __restrict__ rowptr,
                                const int* __restrict__ csr, const float* __restrict__ bias,
                                float* __restrict__ out) {
    const int lane = threadIdx.x & 31;
    const int wrp = threadIdx.x >> 5;
    const int node = blockIdx.x * NPB + wrp;
    if (node >= NNODES) return;
    const int start = rowptr[node];
    const int deg = rowptr[node + 1] - start;
    const float edv = ed[node];

    __shared__ float s_w[NPB][32];
    __shared__ int s_src[NPB][32];

    float sm = 0.f;
    for (int e = lane; e < deg; e += 32) {
        int s = csr[start + e];
        float w = ew(lrelu(es[s] + edv));
        if (e < 32) { s_src[wrp][e] = s; s_w[wrp][e] = w; }
        sm += w;
    }
#pragma unroll
    for (int off = 16; off; off >>= 1) sm += __shfl_xor_sync(0xffffffffu, sm, off);
    const float inv = 1.f / sm;
    __syncwarp();

    float acc = 0.f;
    int cn0 = min(deg, 32);
#pragma unroll 4
    for (int j = 0; j < cn0; j++) {
        acc += s_w[wrp][j] * hbuf[(size_t)s_src[wrp][j] * 32 + lane];
    }
    for (int base = 32; base < deg; base += 32) {
        int cn = min(32, deg - base);
        __syncwarp();
        if (lane < cn) {
            int s = csr[start + base + lane];
            s_src[wrp][lane] = s;
            s_w[wrp][lane] = ew(lrelu(es[s] + edv));
        }
        __syncwarp();
#pragma unroll 4
        for (int j = 0; j < cn; j++) {
            acc += s_w[wrp][j] * hbuf[(size_t)s_src[wrp][j] * 32 + lane];
        }
    }
    float r = acc * inv + bias[lane];
    if (RELU) r = fmaxf(r, 0.f);
    out[(size_t)node * 32 + lane] = r;
}

// ---------------- batchnorm stats (sum / sumsq per channel) ----------------
__global__ void bn_stats_kernel(const float* __restrict__ x, float* __restrict__ stats, int C) {
    __shared__ float shs[512], shq[512];
    int c = threadIdx.x, ry = threadIdx.y;
    int R = blockDim.y;
    int r0 = blockIdx.x * 256;
    int rend = min(r0 + 256, NNODES);
    float s = 0.f, q = 0.f;
    for (int r = r0 + ry; r < rend; r += R) {
        float v = x[(size_t)r * C + c];
        s += v;
        q += v * v;
    }
    int t = ry * C + c;
    shs[t] = s;
    shq[t] = q;
    __syncthreads();
    if (ry == 0) {
        for (int k = 1; k < R; k++) {
            s += shs[k * C + c];
            q += shq[k * C + c];
        }
        atomicAdd(&stats[c], s);
        atomicAdd(&stats[C + c], q);
    }
}

// ---------------- host launch ----------------
extern "C" void kernel_launch(void* const* d_in, const int* in_sizes, int n_in,
                              void* d_out, int out_size) {
    const float* x   = (const float*)d_in[0];
    const int*   ei  = (const int*)d_in[1];
    const float* W1  = (const float*)d_in[2];
    const float* as1 = (const float*)d_in[3];
    const float* ad1 = (const float*)d_in[4];
    const float* b1  = (const float*)d_in[5];
    const float* g1  = (const float*)d_in[6];
    const float* be1 = (const float*)d_in[7];
    const float* W2  = (const float*)d_in[8];
    const float* as2 = (const float*)d_in[9];
    const float* ad2 = (const float*)d_in[10];
    const float* b2  = (const float*)d_in[11];
    const float* g2  = (const float*)d_in[12];
    const float* be2 = (const float*)d_in[13];
    const float* W3  = (const float*)d_in[14];
    const float* as3 = (const float*)d_in[15];
    const float* ad3 = (const float*)d_in[16];
    const float* b3  = (const float*)d_in[17];
    const float* W4  = (const float*)d_in[18];
    const float* as4 = (const float*)d_in[19];
    const float* ad4 = (const float*)d_in[20];
    const float* b4  = (const float*)d_in[21];
    const float* g4  = (const float*)d_in[22];
    const float* be4 = (const float*)d_in[23];
    const float* W5  = (const float*)d_in[24];
    const float* as5 = (const float*)d_in[25];
    const float* ad5 = (const float*)d_in[26];
    const float* b5  = (const float*)d_in[27];
    float* out = (float*)d_out;

    float *h, *bufA, *bufB, *es, *ed, *stats;
    int *deg, *rowptr, *cursor, *csr;
    cudaGetSymbolAddress((void**)&h, g_h);
    cudaGetSymbolAddress((void**)&bufA, g_bufA);
    cudaGetSymbolAddress((void**)&bufB, g_bufB);
    cudaGetSymbolAddress((void**)&es, g_es);
    cudaGetSymbolAddress((void**)&ed, g_ed);
    cudaGetSymbolAddress((void**)&stats, g_stats);
    cudaGetSymbolAddress((void**)&deg, g_deg);
    cudaGetSymbolAddress((void**)&rowptr, g_rowptr);
    cudaGetSymbolAddress((void**)&cursor, g_cursor);
    cudaGetSymbolAddress((void**)&csr, g_csr);

    const int* e_src = ei;
    const int* e_dst = ei + NEDGES;

    // ---- build dst-CSR (shared across all 5 layers) ----
    deg_init_kernel<<<(NNODES + 255) / 256, 256>>>(deg);
    count_kernel<<<(NEDGES + 255) / 256, 256>>>(e_dst, deg);
    scan_kernel<<<1, 1024>>>(deg, rowptr, cursor);
    scatter_self_kernel<<<(NNODES + 255) / 256, 256>>>(cursor, csr);
    scatter_edges_kernel<<<(NEDGES + 255) / 256, 256>>>(e_src, e_dst, cursor, csr);

    const int MBLK = (NNODES + 127) / 128;
    dim3 gblk(16, 16);

    // ---- layer 1: GAT(128 -> 4x32), relu; bn stats ----
    gemm_kernel<128, 128, 32, 8, 8, false, false><<<MBLK, gblk>>>(
        x, W1, h, NNODES, 128, 128, nullptr, nullptr, nullptr);
    attn_kernel<4, 32><<<(NNODES * 4 + 255) / 256, 256>>>(h, as1, ad1, es, ed, NNODES, stats, 256);
    agg_kernel<4, 32, true><<<NNODES, 128>>>(h, es, ed, rowptr, csr, b1, bufA);
    bn_stats_kernel<<<(NNODES + 255) / 256, dim3(128, 4)>>>(bufA, stats, 128);

    // ---- layer 2: bn1 fused into GEMM; GAT(128 -> 4x32), relu; bn stats ----
    gemm_kernel<128, 128, 32, 8, 8, true, false><<<MBLK, gblk>>>(
        bufA, W2, h, NNODES, 128, 128, stats, g1, be1);
    attn_kernel<4, 32><<<(NNODES * 4 + 255) / 256, 256>>>(h, as2, ad2, es, ed, NNODES, stats, 256);
    agg_kernel<4, 32, true><<<NNODES, 128>>>(h, es, ed, rowptr, csr, b2, bufB);
    bn_stats_kernel<<<(NNODES + 255) / 256, dim3(128, 4)>>>(bufB, stats, 128);

    // ---- layer 3: bn2 fused into GEMM; GAT(128 -> 32), relu ----
    gemm_kernel<128, 32, 32, 8, 2, true, false><<<MBLK, gblk>>>(
        bufB, W3, h, NNODES, 128, 32, stats, g2, be2);
    attn_kernel<1, 32><<<(NNODES + 255) / 256, 256>>>(h, as3, ad3, es, ed, NNODES, stats, 0);
    agg_warp_kernel<4, true><<<(NNODES + 3) / 4, 128>>>(h, es, ed, rowptr, csr, b3, bufA);

    // ---- layer 4: GAT(32 -> 32), relu; bn stats ----
    gemm_kernel<128, 32, 32, 8, 2, false, false><<<MBLK, gblk>>>(
        bufA, W4, h, NNODES, 32, 32, nullptr, nullptr, nullptr);
    attn_kernel<1, 32><<<(NNODES + 255) / 256, 256>>>(h, as4, ad4, es, ed, NNODES, stats, 64);
    agg_warp_kernel<4, true><<<(NNODES + 3) / 4, 128>>>(h, es, ed, rowptr, csr, b4, bufB);
    bn_stats_kernel<<<(NNODES + 255) / 256, dim3(32, 16)>>>(bufB, stats, 32);

    // ---- layer 5: relu(bn4) fused into GEMM; GAT(32 -> 128), output ----
    gemm_kernel<128, 128, 32, 8, 8, true, true><<<MBLK, gblk>>>(
        bufB, W5, h, NNODES, 32, 128, stats, g4, be4);
    attn_kernel<1, 128><<<(NNODES + 255) / 256, 256>>>(h, as5, ad5, es, ed, NNODES, stats, 0);
    agg_kernel<1, 128, false><<<NNODES, 128>>>(h, es, ed, rowptr, csr, b5, out);
}

// round 4
// speedup vs baseline: 1.5018x; 1.1072x over previous
#include <cuda_runtime.h>

#define NNODES 50000
#define NEDGES 800000
#define TOTEDGES (NEDGES + NNODES)

// ---------------- scratch (no allocations allowed) ----------------
__device__ float g_h[NNODES * 128];
__device__ float g_bufA[NNODES * 128];
__device__ float g_bufB[NNODES * 128];
__device__ float g_es[NNODES * 4];
__device__ float g_ed[NNODES * 4];
__device__ float g_stats[256];
__device__ int   g_deg[NNODES];
__device__ int   g_rowptr[NNODES + 1];
__device__ int   g_cursor[NNODES];
__device__ int   g_csr[TOTEDGES];

// ---------------- f32x2 helpers ----------------
__device__ __forceinline__ void fma2(unsigned long long& d, unsigned long long a,
                                     unsigned long long b) {
    asm("fma.rn.f32x2 %0, %1, %2, %0;" : "+l"(d) : "l"(a), "l"(b));
}
__device__ __forceinline__ unsigned long long bcast2(float x) {
    unsigned long long r;
    asm("mov.b64 %0, {%1, %1};" : "=l"(r) : "f"(x));
    return r;
}
__device__ __forceinline__ float2 unpack2(unsigned long long p) {
    float2 f;
    asm("mov.b64 {%0, %1}, %2;" : "=f"(f.x), "=f"(f.y) : "l"(p));
    return f;
}

// ---------------- CSR build ----------------
__global__ void deg_init_kernel(int* deg) {
    int i = blockIdx.x * blockDim.x + threadIdx.x;
    if (i < NNODES) deg[i] = 1;  // self loop
}

__global__ void count_kernel(const int* __restrict__ dst, int* __restrict__ deg) {
    int i = blockIdx.x * blockDim.x + threadIdx.x;
    if (i < NEDGES) atomicAdd(&deg[dst[i]], 1);
}

__global__ void scan_kernel(const int* __restrict__ deg, int* __restrict__ rowptr,
                            int* __restrict__ cursor) {
    __shared__ int part[1024];
    const int CH = (NNODES + 1023) / 1024;
    int t = threadIdx.x;
    int base = t * CH;
    int s = 0;
    for (int i = 0; i < CH; i++) {
        int idx = base + i;
        if (idx < NNODES) s += deg[idx];
    }
    part[t] = s;
    __syncthreads();
    for (int off = 1; off < 1024; off <<= 1) {
        int v = (t >= off) ? part[t - off] : 0;
        __syncthreads();
        part[t] += v;
        __syncthreads();
    }
    int run = (t == 0) ? 0 : part[t - 1];
    for (int i = 0; i < CH; i++) {
        int idx = base + i;
        if (idx < NNODES) {
            rowptr[idx] = run;
            cursor[idx] = run;
            run += deg[idx];
        }
    }
    if (t == 1023) rowptr[NNODES] = part[1023];
}

__global__ void scatter_self_kernel(int* __restrict__ cursor, int* __restrict__ csr) {
    int i = blockIdx.x * blockDim.x + threadIdx.x;
    if (i < NNODES) {
        int pos = atomicAdd(&cursor[i], 1);
        csr[pos] = i;
    }
}

__global__ void scatter_edges_kernel(const int* __restrict__ src, const int* __restrict__ dst,
                                     int* __restrict__ cursor, int* __restrict__ csr) {
    int i = blockIdx.x * blockDim.x + threadIdx.x;
    if (i < NEDGES) {
        int d = dst[i];
        int pos = atomicAdd(&cursor[d], 1);
        csr[pos] = src[i];
    }
}

// ---------------- SGEMM with packed f32x2 FMA ----------------
// C[M,N] = A'[M,K] @ B[K,N]; A' optionally BN-affine (+relu) transformed.
// Block = (16,16). BM=128 rows, TM=8 (two groups of 4 contiguous rows -> row-paired
// accumulators fed by ulonglong2 LDS). TN = BN/16 (8 for BN=128, 2 for BN=32).
template <int BN, bool AFFINE, bool INRELU>
__launch_bounds__(256, 2)
__global__ void gemm_kernel(const float* __restrict__ A, const float* __restrict__ B,
                            float* __restrict__ C, int M, int K, int N,
                            const float* __restrict__ stats, const float* __restrict__ g,
                            const float* __restrict__ be) {
    constexpr int BM = 128;
    constexpr int BK = 32;
    constexpr int TN = BN / 16;
    constexpr int LDA = BM + 4;  // 528B row stride: 16B-aligned, de-conflicted

    __shared__ alignas(16) float AsT[BK * LDA];  // transposed A tile [kk][m]
    __shared__ alignas(16) float Bs[BK * BN];
    __shared__ float s_sc[128];
    __shared__ float s_sh[128];

    const int tx = threadIdx.x, ty = threadIdx.y;
    const int t = ty * 16 + tx;
    const int rowBase = blockIdx.x * BM;

    if (AFFINE) {
        const float invn = 1.f / (float)NNODES;
        for (int c = t; c < K; c += 256) {
            float mean = stats[c] * invn;
            float var = stats[K + c] * invn - mean * mean;
            float scv = g[c] * rsqrtf(var + 1e-5f);
            s_sc[c] = scv;
            s_sh[c] = be[c] - mean * scv;
        }
        __syncthreads();
    }

    unsigned long long acc[4][TN];
#pragma unroll
    for (int p = 0; p < 4; p++)
#pragma unroll
        for (int j = 0; j < TN; j++) acc[p][j] = 0ull;

    for (int k0 = 0; k0 < K; k0 += BK) {
        // A tile: load float4 rows, scatter-transpose into AsT
#pragma unroll
        for (int i = t; i < BM * BK / 4; i += 256) {
            int r = i / (BK / 4);
            int kc = (i % (BK / 4)) * 4;
            int rg = rowBase + r;
            float4 v = make_float4(0.f, 0.f, 0.f, 0.f);
            if (rg < M) v = *reinterpret_cast<const float4*>(A + (size_t)rg * K + k0 + kc);
            if (AFFINE) {
                int c = k0 + kc;
                v.x = v.x * s_sc[c] + s_sh[c];
                v.y = v.y * s_sc[c + 1] + s_sh[c + 1];
                v.z = v.z * s_sc[c + 2] + s_sh[c + 2];
                v.w = v.w * s_sc[c + 3] + s_sh[c + 3];
                if (INRELU) {
                    v.x = fmaxf(v.x, 0.f); v.y = fmaxf(v.y, 0.f);
                    v.z = fmaxf(v.z, 0.f); v.w = fmaxf(v.w, 0.f);
                }
            }
            AsT[(kc + 0) * LDA + r] = v.x;
            AsT[(kc + 1) * LDA + r] = v.y;
            AsT[(kc + 2) * LDA + r] = v.z;
            AsT[(kc + 3) * LDA + r] = v.w;
        }
        // B tile
#pragma unroll
        for (int i = t; i < BK * BN / 4; i += 256) {
            int kk = i / (BN / 4);
            int c = (i % (BN / 4)) * 4;
            *reinterpret_cast<float4*>(&Bs[kk * BN + c]) =
                *reinterpret_cast<const float4*>(B + (size_t)(k0 + kk) * N + c);
        }
        __syncthreads();

#pragma unroll
        for (int kk = 0; kk < BK; kk++) {
            const float* arow = &AsT[kk * LDA];
            ulonglong2 aLo = *reinterpret_cast<const ulonglong2*>(arow + ty * 4);
            ulonglong2 aHi = *reinterpret_cast<const ulonglong2*>(arow + 64 + ty * 4);
            unsigned long long bb[TN];
            if (TN == 8) {
                float4 b0 = *reinterpret_cast<const float4*>(&Bs[kk * BN + tx * 4]);
                float4 b1 = *reinterpret_cast<const float4*>(&Bs[kk * BN + 64 + tx * 4]);
                bb[0] = bcast2(b0.x); bb[1] = bcast2(b0.y);
                bb[2] = bcast2(b0.z); bb[3] = bcast2(b0.w);
                bb[4] = bcast2(b1.x); bb[5] = bcast2(b1.y);
                bb[6] = bcast2(b1.z); bb[7] = bcast2(b1.w);
            } else {
                float2 b0 = *reinterpret_cast<const float2*>(&Bs[kk * BN + tx * 2]);
                bb[0] = bcast2(b0.x); bb[1] = bcast2(b0.y);
            }
#pragma unroll
            for (int j = 0; j < TN; j++) {
                fma2(acc[0][j], aLo.x, bb[j]);
                fma2(acc[1][j], aLo.y, bb[j]);
                fma2(acc[2][j], aHi.x, bb[j]);
                fma2(acc[3][j], aHi.y, bb[j]);
            }
        }
        __syncthreads();
    }

    // epilogue: pair p covers rows {r0, r0+1}
#pragma unroll
    for (int p = 0; p < 4; p++) {
        int r0 = rowBase + ((p < 2) ? (ty * 4 + 2 * p) : (64 + ty * 4 + 2 * (p - 2)));
        float2 u[TN];
#pragma unroll
        for (int j = 0; j < TN; j++) u[j] = unpack2(acc[p][j]);
        if (TN == 8) {
            if (r0 < M) {
                *reinterpret_cast<float4*>(C + (size_t)r0 * N + tx * 4) =
                    make_float4(u[0].x, u[1].x, u[2].x, u[3].x);
                *reinterpret_cast<float4*>(C + (size_t)r0 * N + 64 + tx * 4) =
                    make_float4(u[4].x, u[5].x, u[6].x, u[7].x);
            }
            if (r0 + 1 < M) {
                *reinterpret_cast<float4*>(C + (size_t)(r0 + 1) * N + tx * 4) =
                    make_float4(u[0].y, u[1].y, u[2].y, u[3].y);
                *reinterpret_cast<float4*>(C + (size_t)(r0 + 1) * N + 64 + tx * 4) =
                    make_float4(u[4].y, u[5].y, u[6].y, u[7].y);
            }
        } else {
            if (r0 < M)
                *reinterpret_cast<float2*>(C + (size_t)r0 * N + tx * 2) =
                    make_float2(u[0].x, u[1].x);
            if (r0 + 1 < M)
                *reinterpret_cast<float2*>(C + (size_t)(r0 + 1) * N + tx * 2) =
                    make_float2(u[0].y, u[1].y);
        }
    }
}

// ---------------- attention logits (+ fused stats zeroing) ----------------
template <int H, int D>
__global__ void attn_kernel(const float* __restrict__ h, const float* __restrict__ asrc,
                            const float* __restrict__ adst, float* __restrict__ es,
                            float* __restrict__ ed, int n, float* __restrict__ stats, int zn) {
    int idx = blockIdx.x * blockDim.x + threadIdx.x;
    if (idx < zn) stats[idx] = 0.f;
    if (idx >= n * H) return;
    int node = idx / H, hh = idx % H;
    const float4* hp = reinterpret_cast<const float4*>(h + (size_t)node * H * D + hh * D);
    const float4* ap = reinterpret_cast<const float4*>(asrc + hh * D);
    const float4* bp = reinterpret_cast<const float4*>(adst + hh * D);
    float s = 0.f, dv = 0.f;
#pragma unroll
    for (int i = 0; i < D / 4; i++) {
        float4 v = hp[i], a = ap[i], b = bp[i];
        s += v.x * a.x + v.y * a.y + v.z * a.z + v.w * a.w;
        dv += v.x * b.x + v.y * b.y + v.z * b.z + v.w * b.w;
    }
    es[idx] = s;
    ed[idx] = dv;
}

// ---------------- aggregation ----------------
__device__ __forceinline__ float lrelu(float a) { return a > 0.f ? a : 0.2f * a; }
__device__ __forceinline__ float ew(float z) { return __expf(fminf(z, 70.f)); }

template <int H>
__device__ __forceinline__ void load_esv(const float* __restrict__ es, int s, float* v) {
    if constexpr (H == 4) {
        float4 t = *reinterpret_cast<const float4*>(es + s * 4);
        v[0] = t.x; v[1] = t.y; v[2] = t.z; v[3] = t.w;
    } else {
        v[0] = es[s];
    }
}

// block-per-node variant for C = H*D = 128
template <int H, int D, bool RELU>
__global__ void agg_kernel(const float* __restrict__ hbuf, const float* __restrict__ es,
                           const float* __restrict__ ed, const int* __restrict__ rowptr,
                           const int* __restrict__ csr, const float* __restrict__ bias,
                           float* __restrict__ out) {
    constexpr int C = H * D;
    constexpr int NW = C / 32;
    const int node = blockIdx.x;
    const int tid = threadIdx.x;
    const int lane = tid & 31;
    const int wrp = tid >> 5;
    const int start = rowptr[node];
    const int deg = rowptr[node + 1] - start;

    __shared__ float s_ed[H];
    __shared__ float s_inv[H];
    __shared__ float s_red[NW * H];
    __shared__ float s_w[C * H];
    __shared__ int s_src[C];

    if (tid < H) s_ed[tid] = ed[node * H + tid];
    __syncthreads();
    float edv[H];
#pragma unroll
    for (int hh = 0; hh < H; hh++) edv[hh] = s_ed[hh];

    float sm[H];
#pragma unroll
    for (int hh = 0; hh < H; hh++) sm[hh] = 0.f;
    for (int e = tid; e < deg; e += C) {
        int s = csr[start + e];
        float evv[H], w[H];
        load_esv<H>(es, s, evv);
#pragma unroll
        for (int hh = 0; hh < H; hh++) w[hh] = ew(lrelu(evv[hh] + edv[hh]));
        if (e < C) {
            s_src[e] = s;
#pragma unroll
            for (int hh = 0; hh < H; hh++) s_w[e * H + hh] = w[hh];
        }
#pragma unroll
        for (int hh = 0; hh < H; hh++) sm[hh] += w[hh];
    }
#pragma unroll
    for (int hh = 0; hh < H; hh++) {
#pragma unroll
        for (int off = 16; off; off >>= 1) sm[hh] += __shfl_xor_sync(0xffffffffu, sm[hh], off);
    }
    if (lane == 0) {
#pragma unroll
        for (int hh = 0; hh < H; hh++) s_red[wrp * H + hh] = sm[hh];
    }
    __syncthreads();
    if (tid < H) {
        float tsum = 0.f;
#pragma unroll
        for (int w2 = 0; w2 < NW; w2++) tsum += s_red[w2 * H + tid];
        s_inv[tid] = 1.f / tsum;
    }
    __syncthreads();

    const int head = tid / D;
    const float inv = s_inv[head];

    float acc = 0.f;
    int cn0 = min(deg, C);
#pragma unroll 4
    for (int j = 0; j < cn0; j++) {
        acc += s_w[j * H + head] * hbuf[(size_t)s_src[j] * C + tid];
    }
    for (int base = C; base < deg; base += C) {
        int cn = min(C, deg - base);
        __syncthreads();
        if (tid < cn) {
            int s = csr[start + base + tid];
            s_src[tid] = s;
            float evv[H];
            load_esv<H>(es, s, evv);
#pragma unroll
            for (int hh = 0; hh < H; hh++) s_w[tid * H + hh] = ew(lrelu(evv[hh] + edv[hh]));
        }
        __syncthreads();
#pragma unroll 4
        for (int j = 0; j < cn; j++) {
            acc += s_w[j * H + head] * hbuf[(size_t)s_src[j] * C + tid];
        }
    }
    float r = acc * inv + bias[tid];
    if (RELU) r = fmaxf(r, 0.f);
    out[(size_t)node * C + tid] = r;
}

// warp-per-node variant for C = 32 (H=1, D=32)
template <int NPB, bool RELU>
__global__ void agg_warp_kernel(const float* __restrict__ hbuf, const float* __restrict__ es,
                                const float* __restrict__ ed, const int* __restrict__ rowptr,
                                const int* __restrict__ csr, const float* __restrict__ bias,
                                float* __restrict__ out) {
    const int lane = threadIdx.x & 31;
    const int wrp = threadIdx.x >> 5;
    const int node = blockIdx.x * NPB + wrp;
    if (node >= NNODES) return;
    const int start = rowptr[node];
    const int deg = rowptr[node + 1] - start;
    const float edv = ed[node];

    __shared__ float s_w[NPB][32];
    __shared__ int s_src[NPB][32];

    float sm = 0.f;
    for (int e = lane; e < deg; e += 32) {
        int s = csr[start + e];
        float w = ew(lrelu(es[s] + edv));
        if (e < 32) { s_src[wrp][e] = s; s_w[wrp][e] = w; }
        sm += w;
    }
#pragma unroll
    for (int off = 16; off; off >>= 1) sm += __shfl_xor_sync(0xffffffffu, sm, off);
    const float inv = 1.f / sm;
    __syncwarp();

    float acc = 0.f;
    int cn0 = min(deg, 32);
#pragma unroll 4
    for (int j = 0; j < cn0; j++) {
        acc += s_w[wrp][j] * hbuf[(size_t)s_src[wrp][j] * 32 + lane];
    }
    for (int base = 32; base < deg; base += 32) {
        int cn = min(32, deg - base);
        __syncwarp();
        if (lane < cn) {
            int s = csr[start + base + lane];
            s_src[wrp][lane] = s;
            s_w[wrp][lane] = ew(lrelu(es[s] + edv));
        }
        __syncwarp();
#pragma unroll 4
        for (int j = 0; j < cn; j++) {
            acc += s_w[wrp][j] * hbuf[(size_t)s_src[wrp][j] * 32 + lane];
        }
    }
    float r = acc * inv + bias[lane];
    if (RELU) r = fmaxf(r, 0.f);
    out[(size_t)node * 32 + lane] = r;
}

// ---------------- batchnorm stats (sum / sumsq per channel) ----------------
__global__ void bn_stats_kernel(const float* __restrict__ x, float* __restrict__ stats, int C) {
    __shared__ float shs[512], shq[512];
    int c = threadIdx.x, ry = threadIdx.y;
    int R = blockDim.y;
    int r0 = blockIdx.x * 256;
    int rend = min(r0 + 256, NNODES);
    float s = 0.f, q = 0.f;
    for (int r = r0 + ry; r < rend; r += R) {
        float v = x[(size_t)r * C + c];
        s += v;
        q += v * v;
    }
    int t = ry * C + c;
    shs[t] = s;
    shq[t] = q;
    __syncthreads();
    if (ry == 0) {
        for (int k = 1; k < R; k++) {
            s += shs[k * C + c];
            q += shq[k * C + c];
        }
        atomicAdd(&stats[c], s);
        atomicAdd(&stats[C + c], q);
    }
}

// ---------------- host launch ----------------
extern "C" void kernel_launch(void* const* d_in, const int* in_sizes, int n_in,
                              void* d_out, int out_size) {
    const float* x   = (const float*)d_in[0];
    const int*   ei  = (const int*)d_in[1];
    const float* W1  = (const float*)d_in[2];
    const float* as1 = (const float*)d_in[3];
    const float* ad1 = (const float*)d_in[4];
    const float* b1  = (const float*)d_in[5];
    const float* g1  = (const float*)d_in[6];
    const float* be1 = (const float*)d_in[7];
    const float* W2  = (const float*)d_in[8];
    const float* as2 = (const float*)d_in[9];
    const float* ad2 = (const float*)d_in[10];
    const float* b2  = (const float*)d_in[11];
    const float* g2  = (const float*)d_in[12];
    const float* be2 = (const float*)d_in[13];
    const float* W3  = (const float*)d_in[14];
    const float* as3 = (const float*)d_in[15];
    const float* ad3 = (const float*)d_in[16];
    const float* b3  = (const float*)d_in[17];
    const float* W4  = (const float*)d_in[18];
    const float* as4 = (const float*)d_in[19];
    const float* ad4 = (const float*)d_in[20];
    const float* b4  = (const float*)d_in[21];
    const float* g4  = (const float*)d_in[22];
    const float* be4 = (const float*)d_in[23];
    const float* W5  = (const float*)d_in[24];
    const float* as5 = (const float*)d_in[25];
    const float* ad5 = (const float*)d_in[26];
    const float* b5  = (const float*)d_in[27];
    float* out = (float*)d_out;

    float *h, *bufA, *bufB, *es, *ed, *stats;
    int *deg, *rowptr, *cursor, *csr;
    cudaGetSymbolAddress((void**)&h, g_h);
    cudaGetSymbolAddress((void**)&bufA, g_bufA);
    cudaGetSymbolAddress((void**)&bufB, g_bufB);
    cudaGetSymbolAddress((void**)&es, g_es);
    cudaGetSymbolAddress((void**)&ed, g_ed);
    cudaGetSymbolAddress((void**)&stats, g_stats);
    cudaGetSymbolAddress((void**)&deg, g_deg);
    cudaGetSymbolAddress((void**)&rowptr, g_rowptr);
    cudaGetSymbolAddress((void**)&cursor, g_cursor);
    cudaGetSymbolAddress((void**)&csr, g_csr);

    const int* e_src = ei;
    const int* e_dst = ei + NEDGES;

    // ---- build dst-CSR (shared across all 5 layers) ----
    deg_init_kernel<<<(NNODES + 255) / 256, 256>>>(deg);
    count_kernel<<<(NEDGES + 255) / 256, 256>>>(e_dst, deg);
    scan_kernel<<<1, 1024>>>(deg, rowptr, cursor);
    scatter_self_kernel<<<(NNODES + 255) / 256, 256>>>(cursor, csr);
    scatter_edges_kernel<<<(NEDGES + 255) / 256, 256>>>(e_src, e_dst, cursor, csr);

    const int MBLK = (NNODES + 127) / 128;
    dim3 gblk(16, 16);

    // ---- layer 1: GAT(128 -> 4x32), relu; bn stats ----
    gemm_kernel<128, false, false><<<MBLK, gblk>>>(
        x, W1, h, NNODES, 128, 128, nullptr, nullptr, nullptr);
    attn_kernel<4, 32><<<(NNODES * 4 + 255) / 256, 256>>>(h, as1, ad1, es, ed, NNODES, stats, 256);
    agg_kernel<4, 32, true><<<NNODES, 128>>>(h, es, ed, rowptr, csr, b1, bufA);
    bn_stats_kernel<<<(NNODES + 255) / 256, dim3(128, 4)>>>(bufA, stats, 128);

    // ---- layer 2: bn1 fused into GEMM; GAT(128 -> 4x32), relu; bn stats ----
    gemm_kernel<128, true, false><<<MBLK, gblk>>>(
        bufA, W2, h, NNODES, 128, 128, stats, g1, be1);
    attn_kernel<4, 32><<<(NNODES * 4 + 255) / 256, 256>>>(h, as2, ad2, es, ed, NNODES, stats, 256);
    agg_kernel<4, 32, true><<<NNODES, 128>>>(h, es, ed, rowptr, csr, b2, bufB);
    bn_stats_kernel<<<(NNODES + 255) / 256, dim3(128, 4)>>>(bufB, stats, 128);

    // ---- layer 3: bn2 fused into GEMM; GAT(128 -> 32), relu ----
    gemm_kernel<32, true, false><<<MBLK, gblk>>>(
        bufB, W3, h, NNODES, 128, 32, stats, g2, be2);
    attn_kernel<1, 32><<<(NNODES + 255) / 256, 256>>>(h, as3, ad3, es, ed, NNODES, stats, 0);
    agg_warp_kernel<4, true><<<(NNODES + 3) / 4, 128>>>(h, es, ed, rowptr, csr, b3, bufA);

    // ---- layer 4: GAT(32 -> 32), relu; bn stats ----
    gemm_kernel<32, false, false><<<MBLK, gblk>>>(
        bufA, W4, h, NNODES, 32, 32, nullptr, nullptr, nullptr);
    attn_kernel<1, 32><<<(NNODES + 255) / 256, 256>>>(h, as4, ad4, es, ed, NNODES, stats, 64);
    agg_warp_kernel<4, true><<<(NNODES + 3) / 4, 128>>>(h, es, ed, rowptr, csr, b4, bufB);
    bn_stats_kernel<<<(NNODES + 255) / 256, dim3(32, 16)>>>(bufB, stats, 32);

    // ---- layer 5: relu(bn4) fused into GEMM; GAT(32 -> 128), output ----
    gemm_kernel<128, true, true><<<MBLK, gblk>>>(
        bufB, W5, h, NNODES, 32, 128, stats, g4, be4);
    attn_kernel<1, 128><<<(NNODES + 255) / 256, 256>>>(h, as5, ad5, es, ed, NNODES, stats, 0);
    agg_kernel<1, 128, false><<<NNODES, 128>>>(h, es, ed, rowptr, csr, b5, out);
}